// round 13
// baseline (speedup 1.0000x reference)
#include <cuda_runtime.h>

// Math collapse: K and V rows are identical across the sequence dim (age is
// broadcast before the K/V projections), so every score row is constant,
// softmax weights are exactly 1/N, and attended[b,n,:] == age[b]@Wv + bv.
// Output = pixel + broadcast(age @ Wv + bv) over n.
//
// We are at the r+w HBM roofline (~7.4 TB/s combined = 93% spec), so this
// round targets the two non-BW losses:
//  1. SM imbalance: grid 512 x 256thr, 4 CTA/SM cap -> single wave with
//     every SM holding 3-4 CTAs (24-32 warps, all at the BW-saturation knee).
//  2. Preamble exposure: the first stream batch's 8 LDG.128 are issued
//     BEFORE the vb GEMV so its DRAM latency overlaps the Wv loads.

#define B_DIM 8
#define N_DIM 2048
#define D_DIM 768
#define A_DIM 128

#define DCH   8                        // d-chunks of 96 floats
#define NCH   8                        // n-chunks of 256 rows
#define DSUB  96
#define DSUB4 24                       // float4 per d-chunk
#define NROWS 256
#define TPB   256
#define KSPL  2
#define RSTRIDE4 (D_DIM / 4)           // 192 float4 per full row
#define BATCH 8
#define TOTAL4 (NROWS * DSUB4)         // 6144 float4 per block tile

__global__ __launch_bounds__(TPB, 4)   // <=64 regs -> 4 CTA/SM
void fused_cross_attn_kernel(const float* __restrict__ pixel,
                             const float* __restrict__ age,
                             const float* __restrict__ Wv,
                             const float* __restrict__ bv,
                             float* __restrict__ out) {
    __shared__ __align__(16) float s_age[A_DIM];
    __shared__ __align__(16) float s_part[KSPL * DSUB];
    __shared__ __align__(16) float s_vb[DSUB];

    const int tid = threadIdx.x;
    const int dch = blockIdx.x;        // 0..7
    const int nch = blockIdx.y;        // 0..7
    const int b   = blockIdx.z;        // 0..7
    const int d0  = dch * DSUB;

    if (tid < A_DIM) s_age[tid] = age[b * A_DIM + tid];

    // tile base: out[b, n0:n0+256, d0:d0+96]
    const int n0 = nch * NROWS;
    const int tile4 = (b * N_DIM + n0) * RSTRIDE4 + dch * DSUB4;
    const float4* __restrict__ p4 = reinterpret_cast<const float4*>(pixel);
    float4* __restrict__       o4 = reinterpret_cast<float4*>(out);

    // ---- prologue: first stream batch in flight BEFORE the preamble
    float4 r[BATCH];
    int idx0[BATCH];
#pragma unroll
    for (int j = 0; j < BATCH; j++) {
        const int i4 = tid + j * TPB;                  // 0..2047
        const int row = i4 / DSUB4;                    // const-div
        const int c   = i4 - row * DSUB4;
        idx0[j] = tile4 + row * RSTRIDE4 + c;
        r[j] = p4[idx0[j]];
    }
    __syncthreads();                                   // s_age ready

    // ---- preamble: vb slice via split-K x2 (192 threads, 64-long dots)
    if (tid < KSPL * DSUB) {
        const int dl = tid % DSUB;
        const int k  = tid / DSUB;                     // 0..1
        const int dg = d0 + dl;
        float acc = 0.f;
#pragma unroll
        for (int i = 0; i < A_DIM / KSPL; i++) {
            const int a = k * (A_DIM / KSPL) + i;
            acc = fmaf(s_age[a], Wv[a * D_DIM + dg], acc);
        }
        s_part[k * DSUB + dl] = acc;
    }
    __syncthreads();
    if (tid < DSUB) {
        s_vb[tid] = bv[d0 + tid] + (s_part[tid] + s_part[DSUB + tid]);
    }
    __syncthreads();

    const float4* __restrict__ v4 = reinterpret_cast<const float4*>(s_vb);

    // ---- finish prologue batch
#pragma unroll
    for (int j = 0; j < BATCH; j++) {
        const int i4 = tid + j * TPB;
        const int row = i4 / DSUB4;
        const int c   = i4 - row * DSUB4;
        float4 v = v4[c];
        r[j].x += v.x; r[j].y += v.y; r[j].z += v.z; r[j].w += v.w;
        o4[idx0[j]] = r[j];
    }

    // ---- remaining 2 batches (per thread 24 float4 total)
#pragma unroll 1
    for (int base = BATCH * TPB; base < TOTAL4; base += BATCH * TPB) {
        float4 q[BATCH];
        int idx[BATCH], col[BATCH];
#pragma unroll
        for (int j = 0; j < BATCH; j++) {
            const int i4 = base + tid + j * TPB;
            const int row = i4 / DSUB4;
            col[j] = i4 - row * DSUB4;
            idx[j] = tile4 + row * RSTRIDE4 + col[j];
            q[j] = p4[idx[j]];
        }
#pragma unroll
        for (int j = 0; j < BATCH; j++) {
            float4 v = v4[col[j]];
            q[j].x += v.x; q[j].y += v.y; q[j].z += v.z; q[j].w += v.w;
            o4[idx[j]] = q[j];
        }
    }
}

extern "C" void kernel_launch(void* const* d_in, const int* in_sizes, int n_in,
                              void* d_out, int out_size) {
    // metadata order: pixel_features, age_features, Wq, bq, Wk, bk, Wv, bv
    const float* pixel = (const float*)d_in[0];
    const float* age   = (const float*)d_in[1];
    const float* Wv    = (const float*)d_in[6];
    const float* bv    = (const float*)d_in[7];
    float* out = (float*)d_out;

    dim3 grid(DCH, NCH, B_DIM);
    fused_cross_attn_kernel<<<grid, TPB>>>(pixel, age, Wv, bv, out);
}